// round 13
// baseline (speedup 1.0000x reference)
#include <cuda_runtime.h>
#include <cuda_bf16.h>

#define NMAT 512
#define N2   (NMAT * NMAT)
#define RPB  8
#define NB   (NMAT / RPB)   // 64 blocks / chunks

__device__ float    g_B[N2];          // published scaled rows: B~[k][j] = CINV * (row k at time k)
__device__ unsigned g_flag[NB * 32];  // per-chunk publish flag, 128B padded
__device__ double   g_part[NB * 4];   // per-block partial sums

#define CINV 4.248354255291589e-18f   /* exp(-40) */

static __device__ __forceinline__ unsigned ld_acq_u(const unsigned* p) {
    unsigned v;
    asm volatile("ld.acquire.gpu.global.b32 %0, [%1];" : "=r"(v) : "l"(p) : "memory");
    return v;
}
static __device__ __forceinline__ void st_rel_u(unsigned* p, unsigned v) {
    asm volatile("st.release.gpu.global.b32 [%0], %1;" :: "l"(p), "r"(v) : "memory");
}

// ---- packed f32x2 helpers (Blackwell) ----
static __device__ __forceinline__ unsigned long long pk2(float lo, float hi) {
    unsigned long long d;
    asm("mov.b64 %0, {%1, %2};" : "=l"(d) : "r"(__float_as_uint(lo)), "r"(__float_as_uint(hi)));
    return d;
}
static __device__ __forceinline__ void upk2(float& lo, float& hi, unsigned long long v) {
    unsigned a, b;
    asm("mov.b64 {%0, %1}, %2;" : "=r"(a), "=r"(b) : "l"(v));
    lo = __uint_as_float(a); hi = __uint_as_float(b);
}
static __device__ __forceinline__ unsigned long long fma2(unsigned long long a,
                                                          unsigned long long b,
                                                          unsigned long long c) {
    unsigned long long d;
    asm("fma.rn.f32x2 %0, %1, %2, %3;" : "=l"(d) : "l"(a), "l"(b), "l"(c));
    return d;
}

// rank-8 update: f[r] += sum_k A[r][k] * Bt[k]; A packed: s_A2[k][rp] = (A[2rp][k], A[2rp+1][k])
static __device__ __forceinline__ void rank8_update(float (&f)[RPB], const float (&Bt)[RPB],
                                                    const unsigned long long (*s_A2)[4]) {
    unsigned long long acc[4];
#pragma unroll
    for (int rp = 0; rp < 4; rp++) acc[rp] = pk2(f[2*rp], f[2*rp+1]);
#pragma unroll
    for (int k = 0; k < RPB; k++) {
        unsigned long long b2 = pk2(Bt[k], Bt[k]);
        ulonglong2 p0 = ((const ulonglong2*)s_A2[k])[0];
        ulonglong2 p1 = ((const ulonglong2*)s_A2[k])[1];
        acc[0] = fma2(p0.x, b2, acc[0]);
        acc[1] = fma2(p0.y, b2, acc[1]);
        acc[2] = fma2(p1.x, b2, acc[2]);
        acc[3] = fma2(p1.y, b2, acc[3]);
    }
#pragma unroll
    for (int rp = 0; rp < 4; rp++) upk2(f[2*rp], f[2*rp+1], acc[rp]);
}

// ---------------- persistent blocked exp-domain Floyd-Warshall + fused loss
__global__ void __launch_bounds__(NMAT, 1) fw_kernel(const float* __restrict__ sa,
                                                     const float* __restrict__ oa,
                                                     const float* __restrict__ dist,
                                                     const float* __restrict__ flow) {
    const int tid  = threadIdx.x;
    const int b    = blockIdx.x;
    const int base = b * RPB;

    // fused init: F = exp(40 - 10*w0), w0 = dist/(soft+1e-4), diag 0
    float f[RPB];
#pragma unroll
    for (int r = 0; r < RPB; r++) {
        int row = base + r;
        int idx = row * NMAT + tid;
        float w = (row == tid) ? 0.0f : dist[idx] / (sa[idx] + 1e-4f);
        f[r] = __expf(fmaf(-10.0f, w, 40.0f));
    }

    __shared__ __align__(16) float s_h[RPB][RPB];                  // producer corner history
    __shared__ __align__(16) unsigned long long s_A2[2][RPB][4];   // packed A, double-buffered

    for (int c = 0; c < NB; c++) {
        const int k0  = c * RPB;
        const int buf = c & 1;
        const bool owner = (tid >= k0) && (tid < k0 + RPB);   // thread k0+m holds column k0+m
        const int  ms   = tid - k0;                           // m-index if owner
        const int  l0   = k0 & 31;
        const unsigned omask = 0xFFu << l0;
        float Bt[RPB];

        if (c == b) {
            // ---- PRODUCER ----
            if (owner) {
                // corner evolution, column-major in lanes: lane l0+m holds C[:,m] = own f[]
                float cur[RPB], snap[RPB];
#pragma unroll
                for (int r = 0; r < RPB; r++) cur[r] = f[r];
#pragma unroll
                for (int m = 0; m < RPB; m++) {
                    if (ms == m) {
#pragma unroll
                        for (int r = 0; r < RPB; r++) snap[r] = cur[r];   // C[:,m] at time m
                    }
                    float crm[RPB];                        // C[r][m] from lane m (pre-step)
#pragma unroll
                    for (int r = 0; r < RPB; r++) crm[r] = __shfl_sync(omask, cur[r], l0 + m);
                    float s = CINV * cur[m];               // c * C[m][col_self] (pre-step)
#pragma unroll
                    for (int r = 0; r < RPB; r++) cur[r] = fmaf(crm[r], s, cur[r]);
                }
                // hist[k][m] = C[k][m]@time m = lane m's snap[k]; also A[r][k] = hist[r][k]
#pragma unroll
                for (int k = 0; k < RPB; k++) s_h[k][ms] = snap[k];
#pragma unroll
                for (int rp = 0; rp < 4; rp++) s_A2[buf][ms][rp] = pk2(snap[2*rp], snap[2*rp+1]);
            }
            __syncthreads();

            // Bt transform (all threads): Bt[k] = CINV*(f[k] + sum_{m<k} hist[k][m]*Bt[m])
            Bt[0] = f[0] * CINV;
#pragma unroll
            for (int k = 1; k < RPB; k++) {
                float4 ha = *(const float4*)&s_h[k][0];
                float4 hb = *(const float4*)&s_h[k][4];
                float hk[RPB] = {ha.x, ha.y, ha.z, ha.w, hb.x, hb.y, hb.z, hb.w};
                float acc = f[k];
#pragma unroll
                for (int m = 0; m < RPB; m++)
                    if (m < k) acc = fmaf(hk[m], Bt[m], acc);
                Bt[k] = acc * CINV;
            }
#pragma unroll
            for (int k = 0; k < RPB; k++) g_B[(k0 + k) * NMAT + tid] = Bt[k];
            __syncthreads();                       // all STGs ordered before release below
            if (tid == 0) st_rel_u(&g_flag[c * 32], 1u);   // no threadfence: bar + release suffice
        } else {
            // ---- CONSUMER ----
            if (tid < 32) { while (ld_acq_u(&g_flag[c * 32]) == 0u) { } }
            __syncthreads();                       // acquire(warp0) + bar orders all loads

            // wide B loads (MLP 8)
#pragma unroll
            for (int k = 0; k < RPB; k++) Bt[k] = __ldcg(&g_B[(k0 + k) * NMAT + tid]);

            if (owner) {
                // in-warp A solve, column-major: lane l0+k computes A[:,k].
                // c0[r][k] = own f[r] (pre-GEMM); Btc[m][k] = own Bt[m].
                float a[RPB];
#pragma unroll
                for (int r = 0; r < RPB; r++) a[r] = f[r];
#pragma unroll
                for (int m = 0; m < RPB - 1; m++) {
                    float am[RPB];                 // finalized column m
#pragma unroll
                    for (int r = 0; r < RPB; r++) am[r] = __shfl_sync(omask, a[r], l0 + m);
                    if (ms > m) {
                        float bm = Bt[m];
#pragma unroll
                        for (int r = 0; r < RPB; r++) a[r] = fmaf(am[r], bm, a[r]);
                    }
                }
#pragma unroll
                for (int rp = 0; rp < 4; rp++) s_A2[buf][ms][rp] = pk2(a[2*rp], a[2*rp+1]);
            }
            __syncthreads();
        }

        // rank-8 register GEMM (packed f32x2)
        rank8_update(f, Bt, s_A2[buf]);
        // no loop-end barrier: s_A2 double-buffered; next writes to buf^1 are
        // fenced by this iteration's second barrier.
    }

    // ---- fused elementwise loss + reduction over this block's 8 rows (F in regs)
    double s_cost = 0.0, s_util = 0.0, s_ent = 0.0, s_mask = 0.0;
#pragma unroll
    for (int r = 0; r < RPB; r++) {
        int idx = (base + r) * NMAT + tid;
        float s  = sa[idx];
        float d  = dist[idx];
        float fl = flow[idx];
        float o  = oa[idx];

        s_cost += (double)(s * d);
        float eye = (base + r == tid) ? 1.0f : 0.0f;
        float t   = s * (eye - s);
        s_ent  += (double)(t * t);
        s_mask += (double)(s * (1.0f - o));

        float F  = f[r];
        float sp = (F > 1e-37f) ? fmaf(-0.1f, __logf(F), 4.0f) : 1.0e6f;  // w = 4 - 0.1*lnF
        float rail   = __expf(-0.005f * sp);
        float bas    = __expf(-0.01f  * d);
        float choice = rail / (rail + bas);
        float saved  = fmaf(-0.5f, sp, d);
        float u      = fl * choice * saved;
        float elu    = (u > 0.0f) ? u : expm1f(u);
        s_util += (double)(elu + 1.0f);
    }

    const unsigned FULL = 0xffffffffu;
#pragma unroll
    for (int off = 16; off > 0; off >>= 1) {
        s_cost += __shfl_down_sync(FULL, s_cost, off);
        s_util += __shfl_down_sync(FULL, s_util, off);
        s_ent  += __shfl_down_sync(FULL, s_ent , off);
        s_mask += __shfl_down_sync(FULL, s_mask, off);
    }
    __shared__ double red[16][4];
    int wid = tid >> 5, lid = tid & 31;
    if (lid == 0) { red[wid][0]=s_cost; red[wid][1]=s_util; red[wid][2]=s_ent; red[wid][3]=s_mask; }
    __syncthreads();
    if (tid == 0) {
        double a0=0, a1=0, a2=0, a3=0;
#pragma unroll
        for (int w = 0; w < 16; w++) { a0+=red[w][0]; a1+=red[w][1]; a2+=red[w][2]; a3+=red[w][3]; }
        g_part[b*4+0]=a0; g_part[b*4+1]=a1; g_part[b*4+2]=a2; g_part[b*4+3]=a3;
    }
}

// ---------------- final: sum 64 partials, apply entropy scale, write scalar; reset flags
__global__ void final_kernel(const int* __restrict__ epoch_p, float* __restrict__ out) {
    int t = threadIdx.x;   // 32 threads
    double c0 = g_part[t*4+0] + g_part[(t+32)*4+0];
    double c1 = g_part[t*4+1] + g_part[(t+32)*4+1];
    double c2 = g_part[t*4+2] + g_part[(t+32)*4+2];
    double c3 = g_part[t*4+3] + g_part[(t+32)*4+3];
    const unsigned FULL = 0xffffffffu;
#pragma unroll
    for (int off = 16; off > 0; off >>= 1) {
        c0 += __shfl_down_sync(FULL, c0, off);
        c1 += __shfl_down_sync(FULL, c1, off);
        c2 += __shfl_down_sync(FULL, c2, off);
        c3 += __shfl_down_sync(FULL, c3, off);
    }
    // reset publish flags for the next graph replay
    g_flag[t * 32]        = 0u;
    g_flag[(t + 32) * 32] = 0u;
    if (t == 0) {
        int e = *epoch_p;
        double es = (e >= 50) ? 1.0 : (e >= 10) ? 0.1 : (e >= 0) ? 0.05 : 0.0;
        out[0] = (float)(c0 + c1 + c2 * es + 10000.0 * c3);
    }
}

extern "C" void kernel_launch(void* const* d_in, const int* in_sizes, int n_in,
                              void* d_out, int out_size) {
    const float* sa   = (const float*)d_in[0];
    const float* oa   = (const float*)d_in[1];
    const float* dist = (const float*)d_in[2];
    const float* flow = (const float*)d_in[3];
    const int*   ep   = (const int*)  d_in[4];

    fw_kernel<<<NB, NMAT>>>(sa, oa, dist, flow);
    final_kernel<<<1, 32>>>(ep, (float*)d_out);
}

// round 15
// speedup vs baseline: 1.4152x; 1.4152x over previous
#include <cuda_runtime.h>
#include <cuda_bf16.h>

#define NMAT 512
#define N2   (NMAT * NMAT)
#define RPB  8
#define NB   (NMAT / RPB)   // 64 blocks / chunks

__device__ float    g_B[N2];               // published scaled rows: B~[k][j] = CINV*(row k @ time k)
__device__ unsigned g_flag[NB * NB * 32];  // private flag line per (chunk, block), 128B padded
__device__ double   g_part[NB * 4];        // per-block partial sums

#define CINV 4.248354255291589e-18f        /* exp(-40) */

static __device__ __forceinline__ unsigned ld_acq_u(const unsigned* p) {
    unsigned v;
    asm volatile("ld.acquire.gpu.global.b32 %0, [%1];" : "=r"(v) : "l"(p) : "memory");
    return v;
}
static __device__ __forceinline__ void st_rel_u(unsigned* p, unsigned v) {
    asm volatile("st.release.gpu.global.b32 [%0], %1;" :: "l"(p), "r"(v) : "memory");
}

// ---- packed f32x2 helpers (Blackwell) ----
static __device__ __forceinline__ unsigned long long pk2(float lo, float hi) {
    unsigned long long d;
    asm("mov.b64 %0, {%1, %2};" : "=l"(d) : "r"(__float_as_uint(lo)), "r"(__float_as_uint(hi)));
    return d;
}
static __device__ __forceinline__ void upk2(float& lo, float& hi, unsigned long long v) {
    unsigned a, b;
    asm("mov.b64 {%0, %1}, %2;" : "=r"(a), "=r"(b) : "l"(v));
    lo = __uint_as_float(a); hi = __uint_as_float(b);
}
static __device__ __forceinline__ unsigned long long fma2(unsigned long long a,
                                                          unsigned long long b,
                                                          unsigned long long c) {
    unsigned long long d;
    asm("fma.rn.f32x2 %0, %1, %2, %3;" : "=l"(d) : "l"(a), "l"(b), "l"(c));
    return d;
}

// rank-8 update: f[r] += sum_k A[r][k]*Bt[k]; A packed: s_A2[k][rp] = (A[2rp][k], A[2rp+1][k])
static __device__ __forceinline__ void rank8_update(float (&f)[RPB], const float (&Bt)[RPB],
                                                    const unsigned long long (*s_A2)[4]) {
    unsigned long long acc[4];
#pragma unroll
    for (int rp = 0; rp < 4; rp++) acc[rp] = pk2(f[2*rp], f[2*rp+1]);
#pragma unroll
    for (int k = 0; k < RPB; k++) {
        unsigned long long b2 = pk2(Bt[k], Bt[k]);
        ulonglong2 p0 = ((const ulonglong2*)s_A2[k])[0];
        ulonglong2 p1 = ((const ulonglong2*)s_A2[k])[1];
        acc[0] = fma2(p0.x, b2, acc[0]);
        acc[1] = fma2(p0.y, b2, acc[1]);
        acc[2] = fma2(p1.x, b2, acc[2]);
        acc[3] = fma2(p1.y, b2, acc[3]);
    }
#pragma unroll
    for (int rp = 0; rp < 4; rp++) upk2(f[2*rp], f[2*rp+1], acc[rp]);
}

// ---------------- persistent blocked exp-domain Floyd-Warshall + fused loss
__global__ void __launch_bounds__(NMAT, 1) fw_kernel(const float* __restrict__ sa,
                                                     const float* __restrict__ oa,
                                                     const float* __restrict__ dist,
                                                     const float* __restrict__ flow) {
    const int tid  = threadIdx.x;
    const int b    = blockIdx.x;
    const int base = b * RPB;

    // fused init: F = exp(40 - 10*w0), w0 = dist/(soft+1e-4), diag 0
    float f[RPB];
#pragma unroll
    for (int r = 0; r < RPB; r++) {
        int row = base + r;
        int idx = row * NMAT + tid;
        float w = (row == tid) ? 0.0f : dist[idx] / (sa[idx] + 1e-4f);
        f[r] = __expf(fmaf(-10.0f, w, 40.0f));
    }

    __shared__ __align__(16) float s_c0[RPB][RPB];              // own rows at current chunk cols
    __shared__ __align__(16) float s_h [RPB][RPB];              // producer corner history
    __shared__ __align__(16) unsigned long long s_A2[RPB][4];   // packed A coefficients

    // stage c0 for chunk 0 (columns 0..7)
    if (tid < RPB) {
#pragma unroll
        for (int r = 0; r < RPB; r++) s_c0[r][tid] = f[r];
    }
    __syncthreads();

    const unsigned* myflag0 = &g_flag[b * 32];   // poll stride NB*32 per chunk

    for (int c = 0; c < NB; c++) {
        const int k0 = c * RPB;
        float Bt[RPB];

        if (c == b) {
            // ---- PRODUCER ----
            if (tid < 8) {
                // corner evolution (lane r = corner row r), records pre-step history
                float4 q0 = *(const float4*)&s_c0[tid][0];
                float4 q1 = *(const float4*)&s_c0[tid][4];
                float cur[RPB]  = {q0.x,q0.y,q0.z,q0.w,q1.x,q1.y,q1.z,q1.w};
                float hist[RPB];
#pragma unroll
                for (int m = 0; m < RPB; m++) {
                    hist[m] = cur[m];
                    float rowm[RPB];
#pragma unroll
                    for (int cc = 0; cc < RPB; cc++)
                        rowm[cc] = __shfl_sync(0xFFu, cur[cc], m);
                    float cm = cur[m] * CINV;
#pragma unroll
                    for (int cc = 0; cc < RPB; cc++)
                        cur[cc] = fmaf(cm, rowm[cc], cur[cc]);
                }
                *(float4*)&s_h[tid][0] = make_float4(hist[0], hist[1], hist[2], hist[3]);
                *(float4*)&s_h[tid][4] = make_float4(hist[4], hist[5], hist[6], hist[7]);
#pragma unroll
                for (int k = 0; k < RPB; k++) {
                    float hp = __shfl_xor_sync(0xFFu, hist[k], 1);
                    if (!(tid & 1)) s_A2[k][tid >> 1] = pk2(hist[k], hp);
                }
            }
            __syncthreads();

            // Bt transform: Bt[k] = CINV*(f[k] + sum_{m<k} hist[k][m]*Bt[m])
            Bt[0] = f[0] * CINV;
#pragma unroll
            for (int k = 1; k < RPB; k++) {
                float4 h0 = *(const float4*)&s_h[k][0];
                float4 h1 = *(const float4*)&s_h[k][4];
                float hk[RPB] = {h0.x,h0.y,h0.z,h0.w,h1.x,h1.y,h1.z,h1.w};
                float acc = f[k];
#pragma unroll
                for (int m = 0; m < RPB; m++)
                    if (m < k) acc = fmaf(hk[m], Bt[m], acc);
                Bt[k] = acc * CINV;
            }
#pragma unroll
            for (int k = 0; k < RPB; k++) g_B[(k0 + k) * NMAT + tid] = Bt[k];
            __syncthreads();                                 // all data STGs done block-wide
            // fan-out: one private release store per consumer block (no shared hot line)
            if (tid < NB) st_rel_u(&g_flag[(c * NB + tid) * 32], 1u);
        } else {
            // ---- CONSUMER ----
            // every thread spins on its block's PRIVATE flag line; own acquire orders
            // its own subsequent loads -> no post-spin barrier needed.
            const unsigned* fp = myflag0 + c * NB * 32;
            while (ld_acq_u(fp) == 0u) { }

            // wide B loads (MLP 8)
#pragma unroll
            for (int k = 0; k < RPB; k++) Bt[k] = __ldcg(&g_B[(k0 + k) * NMAT + tid]);

            if (tid < 8) {
                // lane m: B~ corner row m via separate loads (overlaps wide loads)
                const float4* gp = (const float4*)&g_B[(k0 + tid) * NMAT + k0];
                float4 q0 = __ldcg(gp);
                float4 q1 = __ldcg(gp + 1);
                float btr[RPB] = {q0.x,q0.y,q0.z,q0.w,q1.x,q1.y,q1.z,q1.w};
                float4 c0a = *(const float4*)&s_c0[tid][0];
                float4 c0b = *(const float4*)&s_c0[tid][4];
                float c0v[RPB] = {c0a.x,c0a.y,c0a.z,c0a.w,c0b.x,c0b.y,c0b.z,c0b.w};
                // A solve: a[k] = c0[r][k] + sum_{m<k} a[m] * Btc[m][k]
                float a[RPB];
                a[0] = c0v[0];
#pragma unroll
                for (int k = 1; k < RPB; k++) {
                    float acc = c0v[k];
#pragma unroll
                    for (int m = 0; m < RPB; m++)
                        if (m < k) acc = fmaf(a[m], __shfl_sync(0xFFu, btr[k], m), acc);
                    a[k] = acc;
                }
#pragma unroll
                for (int k = 0; k < RPB; k++) {
                    float ap = __shfl_xor_sync(0xFFu, a[k], 1);
                    if (!(tid & 1)) s_A2[k][tid >> 1] = pk2(a[k], ap);
                }
            }
            __syncthreads();   // s_A2 ready
        }

        // rank-8 register GEMM (packed f32x2)
        rank8_update(f, Bt, s_A2);

        // stage c0 for the next chunk (post-update values)
        const int nk0 = k0 + RPB;
        if (c + 1 < NB && tid >= nk0 && tid < nk0 + RPB) {
            int col = tid - nk0;
#pragma unroll
            for (int r = 0; r < RPB; r++) s_c0[r][col] = f[r];
        }
        __syncthreads();
    }

    // reset this block's private flag lines for the next graph replay
    // (only this block ever polls them; all producers of all chunks have fired)
    if (tid < NB) g_flag[(tid * NB + b) * 32] = 0u;

    // ---- fused elementwise loss + reduction over this block's 8 rows (F in regs)
    double s_cost = 0.0, s_util = 0.0, s_ent = 0.0, s_mask = 0.0;
#pragma unroll
    for (int r = 0; r < RPB; r++) {
        int idx = (base + r) * NMAT + tid;
        float s  = sa[idx];
        float d  = dist[idx];
        float fl = flow[idx];
        float o  = oa[idx];

        s_cost += (double)(s * d);
        float eye = (base + r == tid) ? 1.0f : 0.0f;
        float t   = s * (eye - s);
        s_ent  += (double)(t * t);
        s_mask += (double)(s * (1.0f - o));

        float F  = f[r];
        float sp = (F > 1e-37f) ? fmaf(-0.1f, __logf(F), 4.0f) : 1.0e6f;  // w = 4 - 0.1*lnF
        float rail   = __expf(-0.005f * sp);
        float bas    = __expf(-0.01f  * d);
        float choice = rail / (rail + bas);
        float saved  = fmaf(-0.5f, sp, d);
        float u      = fl * choice * saved;
        float elu    = (u > 0.0f) ? u : expm1f(u);
        s_util += (double)(elu + 1.0f);
    }

    const unsigned FULL = 0xffffffffu;
#pragma unroll
    for (int off = 16; off > 0; off >>= 1) {
        s_cost += __shfl_down_sync(FULL, s_cost, off);
        s_util += __shfl_down_sync(FULL, s_util, off);
        s_ent  += __shfl_down_sync(FULL, s_ent , off);
        s_mask += __shfl_down_sync(FULL, s_mask, off);
    }
    __shared__ double red[16][4];
    int wid = tid >> 5, lid = tid & 31;
    if (lid == 0) { red[wid][0]=s_cost; red[wid][1]=s_util; red[wid][2]=s_ent; red[wid][3]=s_mask; }
    __syncthreads();
    if (tid == 0) {
        double a0=0, a1=0, a2=0, a3=0;
#pragma unroll
        for (int w = 0; w < 16; w++) { a0+=red[w][0]; a1+=red[w][1]; a2+=red[w][2]; a3+=red[w][3]; }
        g_part[b*4+0]=a0; g_part[b*4+1]=a1; g_part[b*4+2]=a2; g_part[b*4+3]=a3;
    }
}

// ---------------- final: sum 64 partials, apply entropy scale, write scalar
__global__ void final_kernel(const int* __restrict__ epoch_p, float* __restrict__ out) {
    int t = threadIdx.x;   // 32 threads
    double c0 = g_part[t*4+0] + g_part[(t+32)*4+0];
    double c1 = g_part[t*4+1] + g_part[(t+32)*4+1];
    double c2 = g_part[t*4+2] + g_part[(t+32)*4+2];
    double c3 = g_part[t*4+3] + g_part[(t+32)*4+3];
    const unsigned FULL = 0xffffffffu;
#pragma unroll
    for (int off = 16; off > 0; off >>= 1) {
        c0 += __shfl_down_sync(FULL, c0, off);
        c1 += __shfl_down_sync(FULL, c1, off);
        c2 += __shfl_down_sync(FULL, c2, off);
        c3 += __shfl_down_sync(FULL, c3, off);
    }
    if (t == 0) {
        int e = *epoch_p;
        double es = (e >= 50) ? 1.0 : (e >= 10) ? 0.1 : (e >= 0) ? 0.05 : 0.0;
        out[0] = (float)(c0 + c1 + c2 * es + 10000.0 * c3);
    }
}

extern "C" void kernel_launch(void* const* d_in, const int* in_sizes, int n_in,
                              void* d_out, int out_size) {
    const float* sa   = (const float*)d_in[0];
    const float* oa   = (const float*)d_in[1];
    const float* dist = (const float*)d_in[2];
    const float* flow = (const float*)d_in[3];
    const int*   ep   = (const int*)  d_in[4];

    fw_kernel<<<NB, NMAT>>>(sa, oa, dist, flow);
    final_kernel<<<1, 32>>>(ep, (float*)d_out);
}